// round 12
// baseline (speedup 1.0000x reference)
#include <cuda_runtime.h>

#define NXv  440
#define NYv  500
#define GRID (NXv * NYv)          // 220000
#define MAXV 40000
#define MAXP 32
#define NMAX 2000000
#define CAP  32                    // per-cell slots = one 128B line (max cell cnt ~28)
#define NBLK ((GRID + 1023) / 1024)   // 215
#define FULL 0xffffffffu

// out layout (float32): [voxels 40000*32*5][coords 40000*3][num_points 40000]
#define OUT_COORDS (MAXV * MAXP * 5)          // 6,400,000
#define OUT_NUMPTS (OUT_COORDS + MAXV * 3)    // 6,520,000

// g_zero: [0,GRID) = per-cell fill counters, [GRID,GRID+NBLK) = scan flags
__device__ int g_zero[GRID + NBLK];
__device__ int g_cellvox[MAXV];           // packed: (cell<<6) | min(cnt,CAP)
__device__ int g_scratch[GRID * CAP];

__device__ __forceinline__ int cell_of(float x, float y, float z) {
    if (!(x >= 0.0f && x < 70.4f && y >= -40.0f && y < 40.0f &&
          z >= -3.0f && z < 1.0f))
        return -1;
    // match jnp: floor((p - rmin)/vsz) with IEEE f32 division, then clip
    int cx = (int)floorf(__fdiv_rn(x, 0.16f));
    int cy = (int)floorf(__fdiv_rn(y + 40.0f, 0.16f));
    cx = min(max(cx, 0), NXv - 1);
    cy = min(max(cy, 0), NYv - 1);
    return cy * NXv + cx;
}

// 8 points per thread as a software-pipelined pair of quads:
// q0 loads -> q0 cells -> q1 loads issued -> q0 atomics (overlap q1 loads)
// -> q1 cells -> q1 atomics -> stores. Keeps MLP_p1=5 (no L1tex-queue
// blowup) and 8 atomic chains in flight; <=32 regs for full occupancy.
__global__ void __launch_bounds__(256, 8)
k_scatter(const float* __restrict__ pts, int n) {
    int t = blockIdx.x * blockDim.x + threadIdx.x;
    int base = t * 8;
    if (base >= n) return;
    if (base + 8 <= n) {
        const float4* p4 = (const float4*)(pts + (size_t)base * 5);
        // ---- quad 0 loads ----
        float4 a = __ldg(p4 + 0);
        float4 b = __ldg(p4 + 1);
        float4 c = __ldg(p4 + 2);
        float4 d = __ldg(p4 + 3);
        float4 e = __ldg(p4 + 4);
        int c0 = cell_of(a.x, a.y, a.z);
        int c1 = cell_of(b.y, b.z, b.w);
        int c2 = cell_of(c.z, c.w, d.x);
        int c3 = cell_of(d.w, e.x, e.y);
        // ---- quad 1 loads (issued before q0 atomics) ----
        a = __ldg(p4 + 5);
        b = __ldg(p4 + 6);
        c = __ldg(p4 + 7);
        d = __ldg(p4 + 8);
        e = __ldg(p4 + 9);
        // ---- quad 0 atomics (overlap with q1 loads in flight) ----
        int s0 = (c0 >= 0) ? atomicAdd(&g_zero[c0], 1) : CAP;
        int s1 = (c1 >= 0) ? atomicAdd(&g_zero[c1], 1) : CAP;
        int s2 = (c2 >= 0) ? atomicAdd(&g_zero[c2], 1) : CAP;
        int s3 = (c3 >= 0) ? atomicAdd(&g_zero[c3], 1) : CAP;
        // ---- quad 1 cells + atomics ----
        int c4 = cell_of(a.x, a.y, a.z);
        int c5 = cell_of(b.y, b.z, b.w);
        int c6 = cell_of(c.z, c.w, d.x);
        int c7 = cell_of(d.w, e.x, e.y);
        int s4 = (c4 >= 0) ? atomicAdd(&g_zero[c4], 1) : CAP;
        int s5 = (c5 >= 0) ? atomicAdd(&g_zero[c5], 1) : CAP;
        int s6 = (c6 >= 0) ? atomicAdd(&g_zero[c6], 1) : CAP;
        int s7 = (c7 >= 0) ? atomicAdd(&g_zero[c7], 1) : CAP;
        // ---- stores ----
        if (s0 < CAP) g_scratch[(c0 << 5) + s0] = base + 0;
        if (s1 < CAP) g_scratch[(c1 << 5) + s1] = base + 1;
        if (s2 < CAP) g_scratch[(c2 << 5) + s2] = base + 2;
        if (s3 < CAP) g_scratch[(c3 << 5) + s3] = base + 3;
        if (s4 < CAP) g_scratch[(c4 << 5) + s4] = base + 4;
        if (s5 < CAP) g_scratch[(c5 << 5) + s5] = base + 5;
        if (s6 < CAP) g_scratch[(c6 << 5) + s6] = base + 6;
        if (s7 < CAP) g_scratch[(c7 << 5) + s7] = base + 7;
    } else {
        for (int i = base; i < n; i++) {
            float x = __ldg(&pts[(size_t)i * 5 + 0]);
            float y = __ldg(&pts[(size_t)i * 5 + 1]);
            float z = __ldg(&pts[(size_t)i * 5 + 2]);
            int lin = cell_of(x, y, z);
            if (lin < 0) continue;
            int slot = atomicAdd(&g_zero[lin], 1);
            if (slot < CAP) g_scratch[(lin << 5) + slot] = i;
        }
    }
}

// Single-kernel scan with decoupled lookback (all 215 blocks resident:
// spinning on flags cannot deadlock). flag[b] = blocksum+1 once published.
__global__ void k_scan() {
    __shared__ int so[256];
    __shared__ int s_base;
    int tid = threadIdx.x;
    int bid = blockIdx.x;
    int base = bid * 1024 + tid * 4;

    int f4[4], o4[4];
    if (base + 4 <= GRID) {
        int4 f = *(const int4*)&g_zero[base];
        f4[0] = f.x; f4[1] = f.y; f4[2] = f.z; f4[3] = f.w;
    } else {
#pragma unroll
        for (int u = 0; u < 4; u++)
            f4[u] = (base + u < GRID) ? g_zero[base + u] : 0;
    }
    int to = 0;
#pragma unroll
    for (int u = 0; u < 4; u++) { o4[u] = to; to += (f4[u] > 0); }

    so[tid] = to;
    __syncthreads();
    for (int s = 128; s > 0; s >>= 1) {
        if (tid < s) so[tid] += so[tid + s];
        __syncthreads();
    }
    if (tid == 0) atomicExch(&g_zero[GRID + bid], so[0] + 1);  // publish
    __syncthreads();

    int pv = 0;
    if (tid < bid) {
        volatile int* fp = (volatile int*)&g_zero[GRID + tid];
        int f;
        do { f = *fp; } while (f == 0);
        pv = f - 1;
    }
    so[tid] = pv;
    __syncthreads();
    for (int s = 128; s > 0; s >>= 1) {
        if (tid < s) so[tid] += so[tid + s];
        __syncthreads();
    }
    if (tid == 0) s_base = so[0];
    __syncthreads();
    int blockbase = s_base;
    __syncthreads();

    so[tid] = to;
    __syncthreads();
    for (int s = 1; s < 256; s <<= 1) {
        int vo = (tid >= s) ? so[tid - s] : 0;
        __syncthreads();
        so[tid] += vo;
        __syncthreads();
    }
    int ex_o = so[tid] - to + blockbase;
#pragma unroll
    for (int u = 0; u < 4; u++) {
        int idx = base + u;
        if (idx < GRID && f4[u] > 0) {
            int voxid = ex_o + o4[u];
            if (voxid < MAXV)
                g_cellvox[voxid] = (idx << 6) | min(f4[u], CAP);
        }
    }
}

// One warp per KEPT voxel. Packed (cell,cnt); ranks via shuffles; gather into
// smem tile at rank*5 (gcd(5,32)=1 => conflict-free); flush as 40 float4.
__global__ void k_out(const float* __restrict__ pts, float* __restrict__ out) {
    __shared__ float stage[8][160];
    int gt = blockIdx.x * blockDim.x + threadIdx.x;
    int v = gt >> 5;
    int lane = gt & 31;
    int w = threadIdx.x >> 5;
    if (v >= MAXV) return;

    int packed = __ldg(&g_cellvox[v]);
    int cell = packed >> 6;
    int m = packed & 63;              // = min(cnt, 32)

    float4* st4 = (float4*)stage[w];
    st4[lane] = make_float4(0.f, 0.f, 0.f, 0.f);
    if (lane < 8) st4[32 + lane] = make_float4(0.f, 0.f, 0.f, 0.f);

    int v1 = (lane < m) ? g_scratch[(cell << 5) + lane] : 0x7fffffff;

    int r1 = 0;
    for (int k = 0; k < m; k++) {
        int o = __shfl_sync(FULL, v1, k);
        r1 += (o < v1);
    }
    __syncwarp();

    if (lane < m) {
        const float* src = pts + (size_t)v1 * 5;
        float* d = &stage[w][r1 * 5];
#pragma unroll
        for (int t = 0; t < 5; t++) d[t] = __ldg(&src[t]);
    }
    __syncwarp();

    float4* vb = (float4*)(out + (size_t)v * (MAXP * 5));
    vb[lane] = st4[lane];
    if (lane < 8) vb[32 + lane] = st4[32 + lane];

    if (lane == 0) {
        float* oc = out + OUT_COORDS + v * 3;
        oc[0] = 0.0f;                       // z
        oc[1] = (float)(cell / NXv);        // y
        oc[2] = (float)(cell % NXv);        // x
        out[OUT_NUMPTS + v] = (float)m;
    }
}

extern "C" void kernel_launch(void* const* d_in, const int* in_sizes, int n_in,
                              void* d_out, int out_size) {
    const float* pts = (const float*)d_in[0];
    int n = in_sizes[0] / 5;
    if (n > NMAX) n = NMAX;
    float* out = (float*)d_out;

    void* p;
    cudaGetSymbolAddress(&p, g_zero);
    cudaMemsetAsync(p, 0, (GRID + NBLK) * sizeof(int), 0);

    const int TB = 256;
    int no = (n + 7) / 8;
    int nb = (no + TB - 1) / TB;
    k_scatter<<<nb, TB>>>(pts, n);
    k_scan<<<NBLK, 256>>>();
    k_out<<<(MAXV * 32) / TB, TB>>>(pts, out);
}

// round 13
// speedup vs baseline: 1.4022x; 1.4022x over previous
#include <cuda_runtime.h>

#define NXv  440
#define NYv  500
#define GRID (NXv * NYv)          // 220000
#define MAXV 40000
#define MAXP 32
#define NMAX 2000000
#define CAP  32                    // per-cell slots = one 128B line (max cell cnt ~28)
#define NBLK ((GRID + 1023) / 1024)   // 215
#define FULL 0xffffffffu

// out layout (float32): [voxels 40000*32*5][coords 40000*3][num_points 40000]
#define OUT_COORDS (MAXV * MAXP * 5)          // 6,400,000
#define OUT_NUMPTS (OUT_COORDS + MAXV * 3)    // 6,520,000

__device__ int g_zero[GRID];              // per-cell fill counters (self-cleaned by k_scan)
__device__ int g_flags[NBLK];             // lookback scan flags (memset each launch)
__device__ int g_cellvox[MAXV];           // packed: (cell<<6) | min(cnt,CAP)
__device__ int g_scratch[GRID * CAP];

__device__ __forceinline__ int cell_of(float x, float y, float z) {
    if (!(x >= 0.0f && x < 70.4f && y >= -40.0f && y < 40.0f &&
          z >= -3.0f && z < 1.0f))
        return -1;
    // match jnp: floor((p - rmin)/vsz) with IEEE f32 division, then clip
    int cx = (int)floorf(__fdiv_rn(x, 0.16f));
    int cy = (int)floorf(__fdiv_rn(y + 40.0f, 0.16f));
    cx = min(max(cx, 0), NXv - 1);
    cy = min(max(cy, 0), NYv - 1);
    return cy * NXv + cx;
}

__device__ __forceinline__ void bin_point(int i, float x, float y, float z) {
    int lin = cell_of(x, y, z);
    if (lin < 0) return;
    int slot = atomicAdd(&g_zero[lin], 1);
    if (slot < CAP) g_scratch[(lin << 5) + slot] = i;
}

// 2 points per thread (10 floats = 5 x LDG.64, 8B-aligned for every thread).
// 3908 blocks = 3.3 resident waves -> high average occupancy; interleaved
// per-point atomic->store (empirically faster than batching).
__global__ void __launch_bounds__(256, 8)
k_scatter(const float* __restrict__ pts, int n) {
    int t = blockIdx.x * blockDim.x + threadIdx.x;
    int base = t * 2;
    if (base >= n) return;
    if (base + 2 <= n) {
        const float2* p2 = (const float2*)(pts + (size_t)base * 5);
        float2 g0 = __ldg(p2 + 0);   // f0 f1
        float2 g1 = __ldg(p2 + 1);   // f2 f3
        float2 g2 = __ldg(p2 + 2);   // f4 f5
        float2 g3 = __ldg(p2 + 3);   // f6 f7
        bin_point(base + 0, g0.x, g0.y, g1.x);
        bin_point(base + 1, g2.y, g3.x, g3.y);
    } else {
        int i = base;
        float x = __ldg(&pts[(size_t)i * 5 + 0]);
        float y = __ldg(&pts[(size_t)i * 5 + 1]);
        float z = __ldg(&pts[(size_t)i * 5 + 2]);
        bin_point(i, x, y, z);
    }
}

// Single-kernel scan with decoupled lookback (all 215 blocks resident:
// spinning on flags cannot deadlock). flag[b] = blocksum+1 once published.
// Also ZEROES the counters it reads, restoring the g_zero=0 invariant so
// no large memset is needed before the next graph replay.
__global__ void k_scan() {
    __shared__ int so[256];
    __shared__ int s_base;
    int tid = threadIdx.x;
    int bid = blockIdx.x;
    int base = bid * 1024 + tid * 4;

    int f4[4], o4[4];
    if (base + 4 <= GRID) {
        int4 f = *(const int4*)&g_zero[base];
        f4[0] = f.x; f4[1] = f.y; f4[2] = f.z; f4[3] = f.w;
        *(int4*)&g_zero[base] = make_int4(0, 0, 0, 0);   // self-clean
    } else {
#pragma unroll
        for (int u = 0; u < 4; u++) {
            int idx = base + u;
            f4[u] = (idx < GRID) ? g_zero[idx] : 0;
            if (idx < GRID) g_zero[idx] = 0;
        }
    }
    int to = 0;
#pragma unroll
    for (int u = 0; u < 4; u++) { o4[u] = to; to += (f4[u] > 0); }

    so[tid] = to;
    __syncthreads();
    for (int s = 128; s > 0; s >>= 1) {
        if (tid < s) so[tid] += so[tid + s];
        __syncthreads();
    }
    if (tid == 0) atomicExch(&g_flags[bid], so[0] + 1);  // publish
    __syncthreads();

    int pv = 0;
    if (tid < bid) {
        volatile int* fp = (volatile int*)&g_flags[tid];
        int f;
        do { f = *fp; } while (f == 0);
        pv = f - 1;
    }
    so[tid] = pv;
    __syncthreads();
    for (int s = 128; s > 0; s >>= 1) {
        if (tid < s) so[tid] += so[tid + s];
        __syncthreads();
    }
    if (tid == 0) s_base = so[0];
    __syncthreads();
    int blockbase = s_base;
    __syncthreads();

    so[tid] = to;
    __syncthreads();
    for (int s = 1; s < 256; s <<= 1) {
        int vo = (tid >= s) ? so[tid - s] : 0;
        __syncthreads();
        so[tid] += vo;
        __syncthreads();
    }
    int ex_o = so[tid] - to + blockbase;
#pragma unroll
    for (int u = 0; u < 4; u++) {
        int idx = base + u;
        if (idx < GRID && f4[u] > 0) {
            int voxid = ex_o + o4[u];
            if (voxid < MAXV)
                g_cellvox[voxid] = (idx << 6) | min(f4[u], CAP);
        }
    }
}

// One warp per KEPT voxel. Packed (cell,cnt); ranks via shuffles; gather into
// smem tile at rank*5 (gcd(5,32)=1 => conflict-free); flush as 40 float4.
__global__ void k_out(const float* __restrict__ pts, float* __restrict__ out) {
    __shared__ float stage[8][160];
    int gt = blockIdx.x * blockDim.x + threadIdx.x;
    int v = gt >> 5;
    int lane = gt & 31;
    int w = threadIdx.x >> 5;
    if (v >= MAXV) return;

    int packed = __ldg(&g_cellvox[v]);
    int cell = packed >> 6;
    int m = packed & 63;              // = min(cnt, 32)

    float4* st4 = (float4*)stage[w];
    st4[lane] = make_float4(0.f, 0.f, 0.f, 0.f);
    if (lane < 8) st4[32 + lane] = make_float4(0.f, 0.f, 0.f, 0.f);

    int v1 = (lane < m) ? g_scratch[(cell << 5) + lane] : 0x7fffffff;

    int r1 = 0;
    for (int k = 0; k < m; k++) {
        int o = __shfl_sync(FULL, v1, k);
        r1 += (o < v1);
    }
    __syncwarp();

    if (lane < m) {
        const float* src = pts + (size_t)v1 * 5;
        float* d = &stage[w][r1 * 5];
#pragma unroll
        for (int t = 0; t < 5; t++) d[t] = __ldg(&src[t]);
    }
    __syncwarp();

    float4* vb = (float4*)(out + (size_t)v * (MAXP * 5));
    vb[lane] = st4[lane];
    if (lane < 8) vb[32 + lane] = st4[32 + lane];

    if (lane == 0) {
        float* oc = out + OUT_COORDS + v * 3;
        oc[0] = 0.0f;                       // z
        oc[1] = (float)(cell / NXv);        // y
        oc[2] = (float)(cell % NXv);        // x
        out[OUT_NUMPTS + v] = (float)m;
    }
}

extern "C" void kernel_launch(void* const* d_in, const int* in_sizes, int n_in,
                              void* d_out, int out_size) {
    const float* pts = (const float*)d_in[0];
    int n = in_sizes[0] / 5;
    if (n > NMAX) n = NMAX;
    float* out = (float*)d_out;

    void* p;
    cudaGetSymbolAddress(&p, g_flags);
    cudaMemsetAsync(p, 0, NBLK * sizeof(int), 0);   // tiny: 860B

    const int TB = 256;
    int np = (n + 1) / 2;
    int nb = (np + TB - 1) / TB;
    k_scatter<<<nb, TB>>>(pts, n);
    k_scan<<<NBLK, 256>>>();
    k_out<<<(MAXV * 32) / TB, TB>>>(pts, out);
}